// round 13
// baseline (speedup 1.0000x reference)
#include <cuda_runtime.h>
#include <cuda_bf16.h>
#include <cstdint>

#define Bb 8
#define Ss 2048
#define Hh 3584
#define Ee 8
#define Rr 16
#define Kk 2
#define Jj 32
#define SCALING 2.0f

#define NSPLIT 8
#define HSPLIT (Hh / NSPLIT)     // 448
#define KC 16
#define NCH (HSPLIT / KC)        // 28 chunks per split
#define NTOK (Bb * Ss)           // 16384
#define LTOK 128                 // tokens per low CTA

// Scratch (static device globals — no allocation). 16B-aligned (float4 access).
__device__ __align__(16) float g_Ac [(size_t)Bb * Hh * Jj];          // [b][h][j], w*scaling folded
__device__ __align__(16) float g_Bc [(size_t)Bb * Jj * Hh];          // [b][j][h]
__device__ __align__(16) float g_lowp[(size_t)NSPLIT * NTOK * Jj];   // partials [split][tok][j]
__device__ __align__(16) float g_low [(size_t)NTOK * Jj];            // [tok][j]

union U2 { unsigned long long u; float2 f; };

__device__ __forceinline__ unsigned long long fma2(unsigned long long a,
                                                   unsigned long long b,
                                                   unsigned long long c) {
    unsigned long long d;
    asm("fma.rn.f32x2 %0, %1, %2, %3;" : "=l"(d) : "l"(a), "l"(b), "l"(c));
    return d;
}
__device__ __forceinline__ unsigned long long dup2(float v) {
    unsigned long long d;
    asm("mov.b64 %0, {%1, %1};" : "=l"(d) : "f"(v));
    return d;
}
__device__ __forceinline__ uint32_t smem_u32(const void* p) {
    uint32_t a;
    asm("{ .reg .u64 t; cvta.to.shared.u64 t, %1; cvt.u32.u64 %0, t; }"
        : "=r"(a) : "l"(p));
    return a;
}
__device__ __forceinline__ void cp16(uint32_t dst, const void* src) {
    asm volatile("cp.async.cg.shared.global [%0], [%1], 16;"
                 :: "r"(dst), "l"(src) : "memory");
}

// ---------------------------------------------------------------------------
// prep: Ac [b][h][j] (j-fast coalesced) and Bc [b][j][h] (float4-over-r reads).
// grid (Bb, Hh/128), 128 threads.  (R12-measured, unchanged.)
// ---------------------------------------------------------------------------
__global__ void __launch_bounds__(128) prep_kernel(const float* __restrict__ A,
                                                   const float* __restrict__ Bm,
                                                   const float* __restrict__ w,
                                                   const int*   __restrict__ idx)
{
    __shared__ int   es[Jj];
    __shared__ float scs[Jj];
    int b = blockIdx.x;
    int hb = blockIdx.y * 128;
    int tid = threadIdx.x;
    if (tid < Jj) {
        int k = tid >> 4;
        es[tid]  = idx[b * Kk + k];
        scs[tid] = w[b * Kk + k] * SCALING;
    }
    __syncthreads();

#pragma unroll 8
    for (int t = tid; t < 128 * Jj; t += 128) {
        int h = hb + (t >> 5);
        int j = t & 31;
        int r = j & 15;
        g_Ac[((size_t)b * Hh + h) * Jj + j] =
            A[((size_t)(es[j] * Rr + r)) * Hh + h] * scs[j];
    }
#pragma unroll 8
    for (int t = tid; t < 128 * 8; t += 128) {
        int q = t >> 7;
        int h = hb + (t & 127);
        int k = q >> 2;
        int rq = q & 3;
        int e = es[k * 16];
        float4 v = *(const float4*)&Bm[((size_t)e * Hh + h) * Rr + rq * 4];
        size_t o = ((size_t)b * Jj + k * 16 + rq * 4) * Hh + h;
        g_Bc[o]          = v.x;
        g_Bc[o + Hh]     = v.y;
        g_Bc[o + 2 * Hh] = v.z;
        g_Bc[o + 3 * Hh] = v.w;
    }
}

// ---------------------------------------------------------------------------
// low v3: partial low over a k-split. grid (NTOK/128, NSPLIT), 128 threads.
// (R12-measured, unchanged.)
// ---------------------------------------------------------------------------
__global__ void __launch_bounds__(128) low_kernel(const float* __restrict__ x)
{
    __shared__ __align__(16) float xsm[2][LTOK][20];   // [buf][tok][k]; row 80B
    __shared__ __align__(16) float asm_[2][KC][Jj];    // [buf][k][j]

    int tid = threadIdx.x;
    int jg = tid & 3;          // 4 j-groups of 8
    int sg = tid >> 2;         // 32 token-groups (stride-32 tokens)
    int tokbase = blockIdx.x * LTOK;
    int split = blockIdx.y;
    int b = tokbase >> 11;
    int k0base = split * HSPLIT;

    unsigned long long acc[4][4];
#pragma unroll
    for (int c = 0; c < 4; c++)
#pragma unroll
        for (int q = 0; q < 4; q++) acc[c][q] = 0ULL;

    const float* xb = x + (size_t)tokbase * Hh + k0base;
    const float* acb = g_Ac + ((size_t)b * Hh + k0base) * Jj;

    uint32_t uxs = smem_u32(xsm);
    uint32_t uas = smem_u32(asm_);

    int ltok = tid >> 2;
    int lkq  = tid & 3;

#pragma unroll
    for (int i = 0; i < 4; i++) {
        int tok = ltok + 32 * i;
        cp16(uxs + (uint32_t)(tok * 80 + lkq * 16),
             xb + (size_t)tok * Hh + lkq * 4);
    }
    cp16(uas + (uint32_t)(tid * 16), acb + tid * 4);
    asm volatile("cp.async.commit_group;" ::: "memory");

    for (int g = 0; g < NCH; g++) {
        int cur = g & 1;
        __syncthreads();
        if (g + 1 < NCH) {
            int nxt = cur ^ 1;
            uint32_t xoff = uxs + (uint32_t)(nxt * (LTOK * 20 * 4));
            uint32_t aoff = uas + (uint32_t)(nxt * (KC * Jj * 4));
            const float* xg = xb + (size_t)(g + 1) * KC;
            const float* ag = acb + (size_t)(g + 1) * KC * Jj;
#pragma unroll
            for (int i = 0; i < 4; i++) {
                int tok = ltok + 32 * i;
                cp16(xoff + (uint32_t)(tok * 80 + lkq * 16),
                     xg + (size_t)tok * Hh + lkq * 4);
            }
            cp16(aoff + (uint32_t)(tid * 16), ag + tid * 4);
            asm volatile("cp.async.commit_group;" ::: "memory");
            asm volatile("cp.async.wait_group 1;" ::: "memory");
        } else {
            asm volatile("cp.async.wait_group 0;" ::: "memory");
        }
        __syncthreads();

#pragma unroll
        for (int kk4 = 0; kk4 < KC / 4; kk4++) {
            float4 xq[4];
#pragma unroll
            for (int c = 0; c < 4; c++)
                xq[c] = *(const float4*)&xsm[cur][sg + 32 * c][kk4 * 4];
#pragma unroll
            for (int kl = 0; kl < 4; kl++) {
                int kk = kk4 * 4 + kl;
                ulonglong2 a0 = *(const ulonglong2*)&asm_[cur][kk][jg * 8];
                ulonglong2 a1 = *(const ulonglong2*)&asm_[cur][kk][jg * 8 + 4];
#pragma unroll
                for (int c = 0; c < 4; c++) {
                    float xv = (kl == 0) ? xq[c].x : (kl == 1) ? xq[c].y
                             : (kl == 2) ? xq[c].z : xq[c].w;
                    unsigned long long xd = dup2(xv);
                    acc[c][0] = fma2(xd, a0.x, acc[c][0]);
                    acc[c][1] = fma2(xd, a0.y, acc[c][1]);
                    acc[c][2] = fma2(xd, a1.x, acc[c][2]);
                    acc[c][3] = fma2(xd, a1.y, acc[c][3]);
                }
            }
        }
    }

    float* lp = g_lowp + (size_t)split * NTOK * Jj;
#pragma unroll
    for (int c = 0; c < 4; c++) {
        int tok = tokbase + sg + 32 * c;
#pragma unroll
        for (int q = 0; q < 4; q++) {
            U2 u; u.u = acc[c][q];
            *(float2*)&lp[(size_t)tok * Jj + jg * 8 + q * 2] = u.f;
        }
    }
}

// ---------------------------------------------------------------------------
// reduce: sum the NSPLIT partials. grid 256, 256 threads, 8 elems/thread.
// ---------------------------------------------------------------------------
__global__ void __launch_bounds__(256) reduce_kernel()
{
    int base = blockIdx.x * 2048;
#pragma unroll
    for (int r = 0; r < 8; r++) {
        int i = base + r * 256 + threadIdx.x;
        float v = 0.0f;
#pragma unroll
        for (int s = 0; s < NSPLIT; s++)
            v += g_lowp[(size_t)s * NTOK * Jj + i];
        g_low[i] = v;
    }
}

// ---------------------------------------------------------------------------
// out v8: R9 shape + per-pass base register prefetch (hoisted ahead of the
// j-loop; consumed ~2000cyc later) + streaming cache hints (__ldcs base /
// __stcs out) to keep Bc & low L2-resident. launch_bounds(128,5) gives ptxas
// the registers to hold the 8 prefetched float4.
// ---------------------------------------------------------------------------
#define HT 128
#define TT 64

__global__ void __launch_bounds__(128, 5) out_kernel(const float* __restrict__ base,
                                                     float* __restrict__ out)
{
    __shared__ __align__(16) float sB[Jj][HT];        // 16 KB
    __shared__ __align__(16) float sLowF[Jj][68];     // [j][tok]; 8.5 KB

    int tid = threadIdx.x;
    int h0 = blockIdx.y * HT;
    int tok0 = blockIdx.x * TT;
    int b = tok0 >> 11;

    const float* bc = g_Bc + (size_t)b * Jj * Hh + h0;
#pragma unroll
    for (int i = 0; i < 8; i++) {
        int f4 = tid + 128 * i;
        int j = f4 >> 5;
        int hq4 = f4 & 31;
        *(float4*)&sB[j][hq4 * 4] = *(const float4*)&bc[(size_t)j * Hh + hq4 * 4];
    }
#pragma unroll
    for (int i = 0; i < 4; i++) {
        int iv = tid + 128 * i;
        int j = iv & 31;
        int tg = iv >> 5;
        float4 v;
        v.x = g_low[(size_t)(tok0 + tg * 4 + 0) * Jj + j];
        v.y = g_low[(size_t)(tok0 + tg * 4 + 1) * Jj + j];
        v.z = g_low[(size_t)(tok0 + tg * 4 + 2) * Jj + j];
        v.w = g_low[(size_t)(tok0 + tg * 4 + 3) * Jj + j];
        *(float4*)&sLowF[j][tg * 4] = v;
    }
    __syncthreads();

    int hq = tid & 31;        // 32 h-groups of 4 -> 128 h
    int tg = tid >> 5;        // 4 token-groups of 16

#pragma unroll 1
    for (int p = 0; p < 2; p++) {
        int tl = tg * 16 + p * 8;

        // prefetch this pass's 8 base float4 (streaming; consumed post-j-loop)
        float4 bs[8];
#pragma unroll
        for (int t = 0; t < 8; t++) {
            size_t gi = (size_t)(tok0 + tl + t) * Hh + h0 + hq * 4;
            bs[t] = __ldcs((const float4*)&base[gi]);
        }

        unsigned long long acc[4][4];
#pragma unroll
        for (int q = 0; q < 4; q++)
#pragma unroll
            for (int hh = 0; hh < 4; hh++) acc[q][hh] = 0ULL;

#pragma unroll 4
        for (int j = 0; j < Jj; j++) {
            float4 bv = *(const float4*)&sB[j][hq * 4];
            unsigned long long d0 = dup2(bv.x), d1 = dup2(bv.y),
                               d2 = dup2(bv.z), d3 = dup2(bv.w);
#pragma unroll
            for (int m = 0; m < 2; m++) {
                ulonglong2 lq = *(const ulonglong2*)&sLowF[j][tl + m * 4];
                acc[2*m+0][0] = fma2(lq.x, d0, acc[2*m+0][0]);
                acc[2*m+0][1] = fma2(lq.x, d1, acc[2*m+0][1]);
                acc[2*m+0][2] = fma2(lq.x, d2, acc[2*m+0][2]);
                acc[2*m+0][3] = fma2(lq.x, d3, acc[2*m+0][3]);
                acc[2*m+1][0] = fma2(lq.y, d0, acc[2*m+1][0]);
                acc[2*m+1][1] = fma2(lq.y, d1, acc[2*m+1][1]);
                acc[2*m+1][2] = fma2(lq.y, d2, acc[2*m+1][2]);
                acc[2*m+1][3] = fma2(lq.y, d3, acc[2*m+1][3]);
            }
        }

#pragma unroll
        for (int t = 0; t < 8; t++) {
            int q = t >> 1;
            size_t gi = (size_t)(tok0 + tl + t) * Hh + h0 + hq * 4;
            U2 a0, a1, a2, a3;
            a0.u = acc[q][0]; a1.u = acc[q][1]; a2.u = acc[q][2]; a3.u = acc[q][3];
            float4 o;
            if ((t & 1) == 0)
                o = make_float4(bs[t].x + a0.f.x, bs[t].y + a1.f.x,
                                bs[t].z + a2.f.x, bs[t].w + a3.f.x);
            else
                o = make_float4(bs[t].x + a0.f.y, bs[t].y + a1.f.y,
                                bs[t].z + a2.f.y, bs[t].w + a3.f.y);
            __stcs((float4*)&out[gi], o);
        }
    }
}

// ---------------------------------------------------------------------------
extern "C" void kernel_launch(void* const* d_in, const int* in_sizes, int n_in,
                              void* d_out, int out_size)
{
    const float* x    = (const float*)d_in[0];
    const float* base = (const float*)d_in[1];
    const float* lA   = (const float*)d_in[2];
    const float* lB   = (const float*)d_in[3];
    const float* w    = (const float*)d_in[4];
    const int*   idx  = (const int*)  d_in[5];
    float* out = (float*)d_out;

    prep_kernel<<<dim3(Bb, Hh / 128), 128>>>(lA, lB, w, idx);
    low_kernel<<<dim3(NTOK / LTOK, NSPLIT), 128>>>(x);
    reduce_kernel<<<256, 256>>>();
    out_kernel<<<dim3(NTOK / TT, Hh / HT), 128>>>(base, out);
}